// round 16
// baseline (speedup 1.0000x reference)
#include <cuda_runtime.h>

// GlobalFilter: out = irfft2( rfft2(x, ortho) * W, ortho ) per (batch, channel)
// x: [512, 196, 384] f32 ; W: [14, 8, 384, 2] f32 ; out: [512, 196, 384] f32
//
// Round 14: straight-line skewed pipeline over a PAIR of batches.
// 256 threads = 2 groups. P1: all A(b0). P2: G0 B(b0) || G1 A(b1).
// P3: G0 C(b0) || G1 B(b1). P4: all C(b1). fma(B) overlaps DRAM(A/C) by
// construction; NO loops around stages so ptxas keeps twiddles immediate
// (the r12 warp-spec failure mode). Stage math identical to r13/r3.

#define NBATCH 512
#define HALF_W 8
#define NCH    384
#define CT_TILE 16
#define CTP     (CT_TILE + 1)
#define NTHREADS 256

#define C7_TAB {1.0f, 0.6234898018587336f, -0.2225209339563144f, -0.9009688679024191f, \
                -0.9009688679024191f, -0.2225209339563144f, 0.6234898018587336f}
#define S7_TAB {0.0f, 0.7818314824680298f, 0.9749279121818236f, 0.4338837391175581f, \
                -0.4338837391175581f, -0.9749279121818236f, -0.7818314824680298f}
#define CT14_TAB {1.0f, 0.9009688679024191f, 0.6234898018587336f, 0.2225209339563144f, \
                  -0.2225209339563144f, -0.6234898018587336f, -0.9009688679024191f}
#define ST14_TAB {0.0f, 0.4338837391175581f, 0.7818314824680298f, 0.9749279121818236f, \
                  0.9749279121818236f, 0.7818314824680298f, 0.4338837391175581f}

__device__ __forceinline__ float2 mk(float a, float b) { return make_float2(a, b); }

typedef float2 FsBuf[14][HALF_W][CTP];

// Symmetric complex DFT-7 into registers (forward, e^{-2pi i kn/7}).
__device__ __forceinline__ void cdft7_fwd(const float2 v[7], float2 X[7]) {
    const float c7[7] = C7_TAB;
    const float s7[7] = S7_TAB;
    float2 tp[4], tm[4];
#pragma unroll
    for (int n = 1; n <= 3; n++) {
        tp[n] = mk(v[n].x + v[7 - n].x, v[n].y + v[7 - n].y);
        tm[n] = mk(v[n].x - v[7 - n].x, v[n].y - v[7 - n].y);
    }
    X[0] = mk(v[0].x + tp[1].x + tp[2].x + tp[3].x,
              v[0].y + tp[1].y + tp[2].y + tp[3].y);
#pragma unroll
    for (int k = 1; k <= 3; k++) {
        float Ar = v[0].x, Ai = v[0].y, Br = 0.0f, Bi = 0.0f;
#pragma unroll
        for (int n = 1; n <= 3; n++) {
            const int j = (k * n) % 7;
            Ar = fmaf(tp[n].x, c7[j], Ar);
            Ai = fmaf(tp[n].y, c7[j], Ai);
            Br = fmaf(tm[n].x, s7[j], Br);
            Bi = fmaf(tm[n].y, s7[j], Bi);
        }
        X[k] = mk(Ar + Bi, Ai - Br);
        X[7 - k] = mk(Ar - Bi, Ai + Br);
    }
}

// Inverse DFT-7 (e^{+}) storing results straight to (strided) shared memory.
__device__ __forceinline__ void cdft7_store(const float2 v[7], float2* base, const int strideF2) {
    const float c7[7] = C7_TAB;
    const float s7[7] = S7_TAB;
    float2 tp[4], tm[4];
#pragma unroll
    for (int n = 1; n <= 3; n++) {
        tp[n] = mk(v[n].x + v[7 - n].x, v[n].y + v[7 - n].y);
        tm[n] = mk(v[n].x - v[7 - n].x, v[n].y - v[7 - n].y);
    }
    base[0] = mk(v[0].x + tp[1].x + tp[2].x + tp[3].x,
                 v[0].y + tp[1].y + tp[2].y + tp[3].y);
#pragma unroll
    for (int k = 1; k <= 3; k++) {
        float Ar = v[0].x, Ai = v[0].y, Br = 0.0f, Bi = 0.0f;
#pragma unroll
        for (int n = 1; n <= 3; n++) {
            const int j = (k * n) % 7;
            Ar = fmaf(tp[n].x, c7[j], Ar);
            Ai = fmaf(tp[n].y, c7[j], Ai);
            Br = fmaf(tm[n].x, s7[j], Br);
            Bi = fmaf(tm[n].y, s7[j], Bi);
        }
        base[k * strideF2]       = mk(Ar - Bi, Ai + Br);
        base[(7 - k) * strideF2] = mk(Ar + Bi, Ai - Br);
    }
}

// Real forward DFT-7: bins 0..3 (bin 0 purely real).
__device__ __forceinline__ void rdft7(const float r[7], float& R0, float2 R[4]) {
    const float c7[7] = C7_TAB;
    const float s7[7] = S7_TAB;
    float tp[4], tm[4];
#pragma unroll
    for (int n = 1; n <= 3; n++) { tp[n] = r[n] + r[7 - n]; tm[n] = r[n] - r[7 - n]; }
    R0 = r[0] + tp[1] + tp[2] + tp[3];
#pragma unroll
    for (int k = 1; k <= 3; k++) {
        float re = r[0], im = 0.0f;
#pragma unroll
        for (int n = 1; n <= 3; n++) {
            const int j = (k * n) % 7;
            re = fmaf(tp[n],  c7[j], re);
            im = fmaf(tm[n], -s7[j], im);
        }
        R[k] = mk(re, im);
    }
}

// ---- Stage A: row rfft-14 over n2 (224 tasks, start t0 stride str) ----
__device__ __forceinline__ void stage_a(const float* __restrict__ x, int b, int c0,
                                        FsBuf& Fs, int t0, int str) {
    const float ct[7] = CT14_TAB;
    const float st[7] = ST14_TAB;
    for (int t = t0; t < 14 * CT_TILE; t += str) {
        const int c  = t & (CT_TILE - 1);
        const int n1 = t / CT_TILE;
        const float* xrow = x + ((size_t)(b * 196 + n1 * 14)) * NCH + c0 + c;
        float in[14];
#pragma unroll
        for (int n = 0; n < 14; n++) in[n] = xrow[n * NCH];

        float ev[7], od[7];
#pragma unroll
        for (int n = 0; n < 7; n++) { ev[n] = in[2 * n]; od[n] = in[2 * n + 1]; }
        float E0, O0;
        float2 E[4], O[4];
        rdft7(ev, E0, E);
        rdft7(od, O0, O);

        Fs[n1][0][c] = mk(E0 + O0, 0.0f);
        Fs[n1][7][c] = mk(E0 - O0, 0.0f);
#pragma unroll
        for (int k = 1; k <= 3; k++) {  // F[k] = E[k] + (c - i s) O[k]
            const float tr = fmaf(ct[k], O[k].x,  st[k] * O[k].y);
            const float ti = fmaf(ct[k], O[k].y, -st[k] * O[k].x);
            Fs[n1][k][c] = mk(E[k].x + tr, E[k].y + ti);
        }
#pragma unroll
        for (int k = 4; k <= 6; k++) {  // conj-symmetry of E,O
            const float orr = O[7 - k].x, oi = O[7 - k].y;
            const float tr =  fmaf(ct[k], orr, -st[k] * oi);
            const float ti = -fmaf(ct[k], oi,   st[k] * orr);
            Fs[n1][k][c] = mk(E[7 - k].x + tr, -E[7 - k].y + ti);
        }
    }
}

// ---- Stage B: fwd DIT-14 + weight mul + inv DIF-14 in place (t in [0,128)) ----
__device__ __forceinline__ void stage_b(const float* __restrict__ cw, int c0,
                                        FsBuf& Fs, int t) {
    const float ct[7] = CT14_TAB;
    const float st[7] = ST14_TAB;
    const int c  = t & (CT_TILE - 1);
    const int k2 = t / CT_TILE;   // 0..7

    float2 E[7], O[7];
    {
        float2 ve[7];
#pragma unroll
        for (int n = 0; n < 7; n++) ve[n] = Fs[2 * n][k2][c];
        cdft7_fwd(ve, E);
#pragma unroll
        for (int n = 0; n < 7; n++) ve[n] = Fs[2 * n + 1][k2][c];
        cdft7_fwd(ve, O);
    }

    const float2* W = (const float2*)cw + (k2 * NCH + c0 + c);
#pragma unroll
    for (int k = 0; k < 7; k++) {
        float Tr, Ti;
        if (k == 0) { Tr = O[0].x; Ti = O[0].y; }
        else {
            Tr = fmaf(ct[k], O[k].x,  st[k] * O[k].y);
            Ti = fmaf(ct[k], O[k].y, -st[k] * O[k].x);
        }
        const float Gr = E[k].x + Tr, Gi = E[k].y + Ti;   // G[k]
        const float Hr = E[k].x - Tr, Hi = E[k].y - Ti;   // G[k+7]
        const float2 wa = W[k * (HALF_W * NCH)];
        const float2 wb = W[(k + 7) * (HALF_W * NCH)];
        const float gr = fmaf(Gr, wa.x, -Gi * wa.y);
        const float gi = fmaf(Gr, wa.y,  Gi * wa.x);
        const float hr = fmaf(Hr, wb.x, -Hi * wb.y);
        const float hi = fmaf(Hr, wb.y,  Hi * wb.x);
        // DIF fold: p = g+h (even outputs), q = (g-h) e^{+2pi i k/14} (odd)
        E[k] = mk(gr + hr, gi + hi);
        const float dr = gr - hr, di = gi - hi;
        if (k == 0) O[0] = mk(dr, di);
        else O[k] = mk(fmaf(ct[k], dr, -st[k] * di),
                       fmaf(ct[k], di,  st[k] * dr));
    }

    float2* base = &Fs[0][k2][c];
    const int rowF2 = HALF_W * CTP;              // float2 stride per n
    cdft7_store(E, base,          2 * rowF2);    // even n = 2m
    cdft7_store(O, base + rowF2,  2 * rowF2);    // odd  n = 2m+1
}

// ---- Stage C: c2r-14 over k2, write out (224 tasks, start t0 stride str) ----
__device__ __forceinline__ void stage_c(float* __restrict__ out, int b, int c0,
                                        const FsBuf& Fs, int t0, int str) {
    const float c7[7] = C7_TAB;
    const float s7[7] = S7_TAB;
    const float ct[7] = CT14_TAB;
    const float st[7] = ST14_TAB;
    for (int t = t0; t < 14 * CT_TILE; t += str) {
        const int c  = t & (CT_TILE - 1);
        const int n1 = t / CT_TILE;
        float2 V[HALF_W];
#pragma unroll
        for (int k = 0; k < HALF_W; k++) V[k] = Fs[n1][k][c];

        const float a0s = (V[0].x + V[7].x) * (1.0f / 196.0f);
        const float b0s = (V[0].x - V[7].x) * (1.0f / 196.0f);
        float2 a[4], bb[4];
#pragma unroll
        for (int k = 1; k <= 3; k++) {
            a[k] = mk(V[k].x + V[7 - k].x, V[k].y - V[7 - k].y);
            const float dr = V[k].x - V[7 - k].x;
            const float di = V[k].y + V[7 - k].y;
            bb[k] = mk(fmaf(ct[k], dr, -st[k] * di),
                       fmaf(ct[k], di,  st[k] * dr));
        }

        float* orow = out + ((size_t)(b * 196 + n1 * 14)) * NCH + c0 + c;
#pragma unroll
        for (int m = 0; m < 7; m++) {
            float evn = a0s, odd = b0s;
#pragma unroll
            for (int k = 1; k <= 3; k++) {
                const int j = (k * m) % 7;
                evn = fmaf(a[k].x,   c7[j] * (2.0f / 196.0f), evn);
                evn = fmaf(a[k].y,  -s7[j] * (2.0f / 196.0f), evn);
                odd = fmaf(bb[k].x,  c7[j] * (2.0f / 196.0f), odd);
                odd = fmaf(bb[k].y, -s7[j] * (2.0f / 196.0f), odd);
            }
            orow[(2 * m)     * NCH] = evn;
            orow[(2 * m + 1) * NCH] = odd;
        }
    }
}

__global__ __launch_bounds__(NTHREADS, 4)
void gf_kernel(const float* __restrict__ x,
               const float* __restrict__ cw,
               float* __restrict__ out)
{
    __shared__ float2 Fs[2][14][HALF_W][CTP];   // 2 x 15.2 KB

    const int b0  = blockIdx.x * 2;
    const int c0  = blockIdx.y * CT_TILE;
    const int tid = threadIdx.x;
    const int g   = tid >> 7;      // group 0 / 1
    const int t   = tid & 127;

    // zero-cost weight prefetch toward L1 during P1
    if (tid < 14 * HALF_W) {
        const float* wline = cw + ((size_t)tid * NCH + c0) * 2;
        asm volatile("prefetch.global.L1 [%0];" :: "l"(wline));
    }

    // P1: everyone loads+row-transforms batch b0 (224 tasks / 256 threads)
    stage_a(x, b0, c0, Fs[0], tid, NTHREADS);
    __syncthreads();

    // P2: G0 column-transforms b0 (fma) while G1 loads b1 (DRAM)
    if (g == 0) stage_b(cw, c0, Fs[0], t);
    else        stage_a(x, b0 + 1, c0, Fs[1], t, 128);
    __syncthreads();

    // P3: G0 stores b0 (DRAM) while G1 column-transforms b1 (fma)
    if (g == 0) stage_c(out, b0, c0, Fs[0], t, 128);
    else        stage_b(cw, c0, Fs[1], t);
    __syncthreads();

    // P4: everyone stores batch b1
    stage_c(out, b0 + 1, c0, Fs[1], tid, NTHREADS);
}

extern "C" void kernel_launch(void* const* d_in, const int* in_sizes, int n_in,
                              void* d_out, int out_size)
{
    const float* x  = (const float*)d_in[0];
    const float* cw = (const float*)d_in[1];
    float* out = (float*)d_out;
    (void)in_sizes; (void)n_in; (void)out_size;

    dim3 grid(NBATCH / 2, NCH / CT_TILE);
    gf_kernel<<<grid, NTHREADS>>>(x, cw, out);
}

// round 17
// speedup vs baseline: 1.0041x; 1.0041x over previous
#include <cuda_runtime.h>

// GlobalFilter: out = irfft2( rfft2(x, ortho) * W, ortho ) per (batch, channel)
// x: [512, 196, 384] f32 ; W: [14, 8, 384, 2] f32 ; out: [512, 196, 384] f32
//
// Round 15 (final polish): r13 consolidation base (round-3 structure,
// 64 regs / 128 thr / 8 CTAs per SM — the measured optimum across 10
// structural experiments) + __stcs streaming stores for the write-once
// output so L2 keeps the reused weight/x lines instead.

#define NBATCH 512
#define HALF_W 8
#define NCH    384
#define CT_TILE 16
#define CTP     (CT_TILE + 1)   // padded smem channel dim
#define NTHREADS 128

#define C7_TAB {1.0f, 0.6234898018587336f, -0.2225209339563144f, -0.9009688679024191f, \
                -0.9009688679024191f, -0.2225209339563144f, 0.6234898018587336f}
#define S7_TAB {0.0f, 0.7818314824680298f, 0.9749279121818236f, 0.4338837391175581f, \
                -0.4338837391175581f, -0.9749279121818236f, -0.7818314824680298f}
#define CT14_TAB {1.0f, 0.9009688679024191f, 0.6234898018587336f, 0.2225209339563144f, \
                  -0.2225209339563144f, -0.6234898018587336f, -0.9009688679024191f}
#define ST14_TAB {0.0f, 0.4338837391175581f, 0.7818314824680298f, 0.9749279121818236f, \
                  0.9749279121818236f, 0.7818314824680298f, 0.4338837391175581f}

__device__ __forceinline__ float2 mk(float a, float b) { return make_float2(a, b); }

// Symmetric complex DFT-7 into registers. SGN=-1: e^{-2pi i kn/7}; +1: e^{+}.
template<int SGN>
__device__ __forceinline__ void cdft7(const float2 v[7], float2 X[7]) {
    const float c7[7] = C7_TAB;
    const float s7[7] = S7_TAB;
    float2 tp[4], tm[4];
#pragma unroll
    for (int n = 1; n <= 3; n++) {
        tp[n] = mk(v[n].x + v[7 - n].x, v[n].y + v[7 - n].y);
        tm[n] = mk(v[n].x - v[7 - n].x, v[n].y - v[7 - n].y);
    }
    X[0] = mk(v[0].x + tp[1].x + tp[2].x + tp[3].x,
              v[0].y + tp[1].y + tp[2].y + tp[3].y);
#pragma unroll
    for (int k = 1; k <= 3; k++) {
        float Ar = v[0].x, Ai = v[0].y, Br = 0.0f, Bi = 0.0f;
#pragma unroll
        for (int n = 1; n <= 3; n++) {
            const int j = (k * n) % 7;
            Ar = fmaf(tp[n].x, c7[j], Ar);
            Ai = fmaf(tp[n].y, c7[j], Ai);
            Br = fmaf(tm[n].x, s7[j], Br);
            Bi = fmaf(tm[n].y, s7[j], Bi);
        }
        if (SGN < 0) { X[k] = mk(Ar + Bi, Ai - Br); X[7 - k] = mk(Ar - Bi, Ai + Br); }
        else         { X[k] = mk(Ar - Bi, Ai + Br); X[7 - k] = mk(Ar + Bi, Ai - Br); }
    }
}

// Same DFT-7 but stores results straight to (strided) shared memory.
template<int SGN>
__device__ __forceinline__ void cdft7_store(const float2 v[7], float2* base, const int strideF2) {
    const float c7[7] = C7_TAB;
    const float s7[7] = S7_TAB;
    float2 tp[4], tm[4];
#pragma unroll
    for (int n = 1; n <= 3; n++) {
        tp[n] = mk(v[n].x + v[7 - n].x, v[n].y + v[7 - n].y);
        tm[n] = mk(v[n].x - v[7 - n].x, v[n].y - v[7 - n].y);
    }
    base[0] = mk(v[0].x + tp[1].x + tp[2].x + tp[3].x,
                 v[0].y + tp[1].y + tp[2].y + tp[3].y);
#pragma unroll
    for (int k = 1; k <= 3; k++) {
        float Ar = v[0].x, Ai = v[0].y, Br = 0.0f, Bi = 0.0f;
#pragma unroll
        for (int n = 1; n <= 3; n++) {
            const int j = (k * n) % 7;
            Ar = fmaf(tp[n].x, c7[j], Ar);
            Ai = fmaf(tp[n].y, c7[j], Ai);
            Br = fmaf(tm[n].x, s7[j], Br);
            Bi = fmaf(tm[n].y, s7[j], Bi);
        }
        if (SGN < 0) {
            base[k * strideF2]       = mk(Ar + Bi, Ai - Br);
            base[(7 - k) * strideF2] = mk(Ar - Bi, Ai + Br);
        } else {
            base[k * strideF2]       = mk(Ar - Bi, Ai + Br);
            base[(7 - k) * strideF2] = mk(Ar + Bi, Ai - Br);
        }
    }
}

// Real forward DFT-7: bins 0..3 (bin 0 purely real).
__device__ __forceinline__ void rdft7(const float r[7], float& R0, float2 R[4]) {
    const float c7[7] = C7_TAB;
    const float s7[7] = S7_TAB;
    float tp[4], tm[4];
#pragma unroll
    for (int n = 1; n <= 3; n++) { tp[n] = r[n] + r[7 - n]; tm[n] = r[n] - r[7 - n]; }
    R0 = r[0] + tp[1] + tp[2] + tp[3];
#pragma unroll
    for (int k = 1; k <= 3; k++) {
        float re = r[0], im = 0.0f;
#pragma unroll
        for (int n = 1; n <= 3; n++) {
            const int j = (k * n) % 7;
            re = fmaf(tp[n],  c7[j], re);
            im = fmaf(tm[n], -s7[j], im);
        }
        R[k] = mk(re, im);
    }
}

__global__ __launch_bounds__(NTHREADS, 8)
void gf_kernel(const float* __restrict__ x,
               const float* __restrict__ cw,
               float* __restrict__ out)
{
    __shared__ float2 Fs[14][HALF_W][CTP];   // ~15.2 KB

    const int b   = blockIdx.x;
    const int c0  = blockIdx.y * CT_TILE;
    const int tid = threadIdx.x;

    // Zero-cost: pull the CTA's 112 weight lines (128B each) toward L1
    // while Stage A runs. One instruction, no registers, no barriers.
    if (tid < 14 * HALF_W) {
        const float* wline = cw + ((size_t)tid * NCH + c0) * 2;
        asm volatile("prefetch.global.L1 [%0];" :: "l"(wline));
    }

    // ---------------- Stage A: row rfft-14 over n2 ----------------
    {
        const float ct[7] = CT14_TAB;
        const float st[7] = ST14_TAB;
        for (int t = tid; t < 14 * CT_TILE; t += NTHREADS) {
            const int c  = t & (CT_TILE - 1);
            const int n1 = t / CT_TILE;
            const float* xrow = x + ((size_t)(b * 196 + n1 * 14)) * NCH + c0 + c;
            float in[14];
#pragma unroll
            for (int n = 0; n < 14; n++) in[n] = xrow[n * NCH];

            float ev[7], od[7];
#pragma unroll
            for (int n = 0; n < 7; n++) { ev[n] = in[2 * n]; od[n] = in[2 * n + 1]; }
            float E0, O0;
            float2 E[4], O[4];
            rdft7(ev, E0, E);
            rdft7(od, O0, O);

            Fs[n1][0][c] = mk(E0 + O0, 0.0f);
            Fs[n1][7][c] = mk(E0 - O0, 0.0f);
#pragma unroll
            for (int k = 1; k <= 3; k++) {  // F[k] = E[k] + (c - i s) O[k]
                const float tr = fmaf(ct[k], O[k].x,  st[k] * O[k].y);
                const float ti = fmaf(ct[k], O[k].y, -st[k] * O[k].x);
                Fs[n1][k][c] = mk(E[k].x + tr, E[k].y + ti);
            }
#pragma unroll
            for (int k = 4; k <= 6; k++) {  // E'[k]=conj(E[7-k]), O'[k]=conj(O[7-k])
                const float orr = O[7 - k].x, oi = O[7 - k].y;
                const float tr =  fmaf(ct[k], orr, -st[k] * oi);
                const float ti = -fmaf(ct[k], oi,   st[k] * orr);
                Fs[n1][k][c] = mk(E[7 - k].x + tr, -E[7 - k].y + ti);
            }
        }
    }
    __syncthreads();

    // ---- Stage B: fwd DIT-14 + weight mul + inv DIF-14, in-place pairs ----
    {
        const float ct[7] = CT14_TAB;
        const float st[7] = ST14_TAB;
        const int c  = tid & (CT_TILE - 1);
        const int k2 = tid / CT_TILE;   // 0..7

        float2 E[7], O[7];
        {
            float2 ve[7];
#pragma unroll
            for (int n = 0; n < 7; n++) ve[n] = Fs[2 * n][k2][c];
            cdft7<-1>(ve, E);
#pragma unroll
            for (int n = 0; n < 7; n++) ve[n] = Fs[2 * n + 1][k2][c];
            cdft7<-1>(ve, O);
        }

        // 32-bit weight indexing: whole tensor is 344k float2, offsets fit
        const float2* W = (const float2*)cw + (k2 * NCH + c0 + c);
#pragma unroll
        for (int k = 0; k < 7; k++) {
            float Tr, Ti;
            if (k == 0) { Tr = O[0].x; Ti = O[0].y; }
            else {
                Tr = fmaf(ct[k], O[k].x,  st[k] * O[k].y);
                Ti = fmaf(ct[k], O[k].y, -st[k] * O[k].x);
            }
            const float Gr = E[k].x + Tr, Gi = E[k].y + Ti;   // G[k]
            const float Hr = E[k].x - Tr, Hi = E[k].y - Ti;   // G[k+7]
            const float2 wa = W[k * (HALF_W * NCH)];
            const float2 wb = W[(k + 7) * (HALF_W * NCH)];
            const float gr = fmaf(Gr, wa.x, -Gi * wa.y);
            const float gi = fmaf(Gr, wa.y,  Gi * wa.x);
            const float hr = fmaf(Hr, wb.x, -Hi * wb.y);
            const float hi = fmaf(Hr, wb.y,  Hi * wb.x);
            // DIF fold: p = g+h (even outputs), q = (g-h) e^{+2pi i k/14} (odd)
            E[k] = mk(gr + hr, gi + hi);
            const float dr = gr - hr, di = gi - hi;
            if (k == 0) O[0] = mk(dr, di);
            else O[k] = mk(fmaf(ct[k], dr, -st[k] * di),
                           fmaf(ct[k], di,  st[k] * dr));
        }

        float2* base = &Fs[0][k2][c];
        const int rowF2 = HALF_W * CTP;              // float2 stride per n
        cdft7_store<1>(E, base,          2 * rowF2); // even n = 2m
        cdft7_store<1>(O, base + rowF2,  2 * rowF2); // odd  n = 2m+1
    }
    __syncthreads();

    // ---------------- Stage C: c2r-14 over k2, streaming stores ----------------
    {
        const float c7[7] = C7_TAB;
        const float s7[7] = S7_TAB;
        const float ct[7] = CT14_TAB;
        const float st[7] = ST14_TAB;
        for (int t = tid; t < 14 * CT_TILE; t += NTHREADS) {
            const int c  = t & (CT_TILE - 1);
            const int n1 = t / CT_TILE;
            float2 V[HALF_W];
#pragma unroll
            for (int k = 0; k < HALF_W; k++) V[k] = Fs[n1][k][c];

            // fold k / k+7: a_k conj-symmetric part, b_k twiddled difference
            const float a0s = (V[0].x + V[7].x) * (1.0f / 196.0f);
            const float b0s = (V[0].x - V[7].x) * (1.0f / 196.0f);
            float2 a[4], bb[4];
#pragma unroll
            for (int k = 1; k <= 3; k++) {
                a[k] = mk(V[k].x + V[7 - k].x, V[k].y - V[7 - k].y);
                const float dr = V[k].x - V[7 - k].x;
                const float di = V[k].y + V[7 - k].y;
                bb[k] = mk(fmaf(ct[k], dr, -st[k] * di),
                           fmaf(ct[k], di,  st[k] * dr));
            }

            float* orow = out + ((size_t)(b * 196 + n1 * 14)) * NCH + c0 + c;
#pragma unroll
            for (int m = 0; m < 7; m++) {
                float evn = a0s, odd = b0s;
#pragma unroll
                for (int k = 1; k <= 3; k++) {
                    const int j = (k * m) % 7;
                    evn = fmaf(a[k].x,   c7[j] * (2.0f / 196.0f), evn);
                    evn = fmaf(a[k].y,  -s7[j] * (2.0f / 196.0f), evn);
                    odd = fmaf(bb[k].x,  c7[j] * (2.0f / 196.0f), odd);
                    odd = fmaf(bb[k].y, -s7[j] * (2.0f / 196.0f), odd);
                }
                // write-once output: evict-first so L2 keeps weights/x instead
                __stcs(&orow[(2 * m)     * NCH], evn);
                __stcs(&orow[(2 * m + 1) * NCH], odd);
            }
        }
    }
}

extern "C" void kernel_launch(void* const* d_in, const int* in_sizes, int n_in,
                              void* d_out, int out_size)
{
    const float* x  = (const float*)d_in[0];
    const float* cw = (const float*)d_in[1];
    float* out = (float*)d_out;
    (void)in_sizes; (void)n_in; (void)out_size;

    dim3 grid(NBATCH, NCH / CT_TILE);
    gf_kernel<<<grid, NTHREADS>>>(x, cw, out);
}